// round 4
// baseline (speedup 1.0000x reference)
#include <cuda_runtime.h>

// Depthwise 3x3 conv with hard-one-hot kernel == pure spatial shift, zero pad:
//   out[b,c,h,w] = x[b,c, h+dy, w+dx],  (dy,dx) = argmax(|weight|) - 1
//
// One warp per image row (W=256 -> 2 aligned float4/lane). Horizontal shift
// via register shuffle (value shuffled past lane 0/31 is exactly the zero
// padding). Streaming loads/stores (__ldcs/__stcs): zero reuse either way, so
// evict-first keeps the read and write streams from thrashing L2.
// Argmax of the 9 weights is computed per-thread (uniform address -> one
// sector, L2-hot) to avoid a block barrier + smem on the critical path.

__global__ __launch_bounds__(256) void shift_row_kernel(
    const float* __restrict__ x, const float* __restrict__ w9,
    float* __restrict__ out)
{
    // 9-element abs-argmax, first occurrence wins (matches jnp.argmax)
    float best = -1.0f;
    int bi = 0;
    #pragma unroll
    for (int i = 0; i < 9; ++i) {
        float a = fabsf(__ldg(w9 + i));
        if (a > best) { best = a; bi = i; }
    }
    const int dy = bi / 3 - 1;
    const int dx = bi % 3 - 1;

    const int gw   = (blockIdx.x * blockDim.x + threadIdx.x) >> 5;  // row id
    const int lane = threadIdx.x & 31;

    const int h  = gw & 255;                   // row within plane
    const int sh = h + dy;
    const size_t plane = (size_t)(gw >> 8);    // fused b*c plane

    float4 o0, o1;
    if ((unsigned)sh < 256u) {                 // warp-uniform
        const float4* src = reinterpret_cast<const float4*>(
            x + ((plane << 8) + (size_t)sh) * 256) + (lane << 1);
        float4 r0 = __ldcs(src);
        float4 r1 = __ldcs(src + 1);
        if (dx == 0) {
            o0 = r0; o1 = r1;
        } else if (dx > 0) {
            float nxt = __shfl_down_sync(0xffffffffu, r0.x, 1);
            if (lane == 31) nxt = 0.0f;        // col 256 -> zero pad
            o0 = make_float4(r0.y, r0.z, r0.w, r1.x);
            o1 = make_float4(r1.y, r1.z, r1.w, nxt);
        } else {
            float prv = __shfl_up_sync(0xffffffffu, r1.w, 1);
            if (lane == 0) prv = 0.0f;         // col -1 -> zero pad
            o0 = make_float4(prv, r0.x, r0.y, r0.z);
            o1 = make_float4(r0.w, r1.x, r1.y, r1.z);
        }
    } else {
        o0 = make_float4(0.f, 0.f, 0.f, 0.f);
        o1 = o0;
    }

    float4* dst = reinterpret_cast<float4*>(out) + ((size_t)gw << 6) + (lane << 1);
    __stcs(dst, o0);
    __stcs(dst + 1, o1);
}

extern "C" void kernel_launch(void* const* d_in, const int* in_sizes, int n_in,
                              void* d_out, int out_size) {
    const float* x = (const float*)d_in[0];
    const float* w = (const float*)d_in[1];
    float* out = (float*)d_out;

    int nrows  = out_size >> 8;     // 262144 rows
    int blocks = nrows >> 3;        // 8 warps (rows) per 256-thread block
    shift_row_kernel<<<blocks, 256>>>(x, w, out);
}

// round 6
// speedup vs baseline: 1.0082x; 1.0082x over previous
#include <cuda_runtime.h>

// Depthwise 3x3 conv with hard-one-hot kernel == pure spatial shift, zero pad:
//   out[b,c,h,w] = x[b,c, h+dy, w+dx],  (dy,dx) = argmax(|weight|) - 1
//
// Best structure (R2): one warp per image row, aligned float4 load/store,
// horizontal shift via register shuffle (value shuffled past lane 0/31 is
// exactly the zero padding), argmax once per block in smem.
// This round's single change: streaming cache hints (__ldcs/__stcs) on the
// bulk traffic — zero reuse in either stream, keep L2 as pass-through.

__global__ __launch_bounds__(256) void shift_row_kernel(
    const float* __restrict__ x, const float* __restrict__ w9,
    float* __restrict__ out)
{
    __shared__ int2 s_shift;
    if (threadIdx.x == 0) {
        float best = -1.0f;
        int bi = 0;
        #pragma unroll
        for (int i = 0; i < 9; ++i) {
            float a = fabsf(w9[i]);
            if (a > best) { best = a; bi = i; }   // first occurrence wins (jnp.argmax)
        }
        s_shift = make_int2(bi / 3 - 1, bi % 3 - 1);
    }
    __syncthreads();
    const int dy = s_shift.x;
    const int dx = s_shift.y;

    const int gw   = (blockIdx.x * blockDim.x + threadIdx.x) >> 5;  // row id
    const int lane = threadIdx.x & 31;

    const int h  = gw & 255;                   // row within plane
    const int sh = h + dy;
    const size_t plane = (size_t)(gw >> 8);    // fused b*c plane

    float4 o0, o1;
    if ((unsigned)sh < 256u) {                 // warp-uniform
        const float4* src = reinterpret_cast<const float4*>(
            x + ((plane << 8) + (size_t)sh) * 256) + (lane << 1);
        float4 r0 = __ldcs(src);
        float4 r1 = __ldcs(src + 1);
        if (dx == 0) {
            o0 = r0; o1 = r1;
        } else if (dx > 0) {
            float nxt = __shfl_down_sync(0xffffffffu, r0.x, 1);
            if (lane == 31) nxt = 0.0f;        // col 256 -> zero pad
            o0 = make_float4(r0.y, r0.z, r0.w, r1.x);
            o1 = make_float4(r1.y, r1.z, r1.w, nxt);
        } else {
            float prv = __shfl_up_sync(0xffffffffu, r1.w, 1);
            if (lane == 0) prv = 0.0f;         // col -1 -> zero pad
            o0 = make_float4(prv, r0.x, r0.y, r0.z);
            o1 = make_float4(r0.w, r1.x, r1.y, r1.z);
        }
    } else {
        o0 = make_float4(0.f, 0.f, 0.f, 0.f);
        o1 = o0;
    }

    float4* dst = reinterpret_cast<float4*>(out) + ((size_t)gw << 6) + (lane << 1);
    __stcs(dst, o0);
    __stcs(dst + 1, o1);
}

extern "C" void kernel_launch(void* const* d_in, const int* in_sizes, int n_in,
                              void* d_out, int out_size) {
    const float* x = (const float*)d_in[0];
    const float* w = (const float*)d_in[1];
    float* out = (float*)d_out;

    int nrows  = out_size >> 8;     // 262144 rows
    int blocks = nrows >> 3;        // 8 warps (rows) per 256-thread block
    shift_row_kernel<<<blocks, 256>>>(x, w, out);
}